// round 1
// baseline (speedup 1.0000x reference)
#include <cuda_runtime.h>
#include <math_constants.h>

#define BB 2
#define NN 8192
#define SS 4096
#define IN_CH 64
#define TRANS_CH 64
#define OUT_CH 128
#define TP 8          // sampled points per block in fused kernel

// ---------------- device scratch (no cudaMalloc allowed) ----------------
__device__ float4 g_xyzw[BB * NN];      // x,y,z,|x|^2
__device__ float4 g_sxyzw[BB * SS];     // sampled gather
__device__ int    g_aidx[BB * NN * 4];  // global knn top-4 indices
__device__ float  g_adist[BB * NN * 4]; // global knn top-4 dists (sqrt)
__device__ int    g_saidx[BB * SS * 4]; // sampled-space knn top-4 indices
__device__ float  g_sadist[BB * SS * 4];

// ---------------- helpers ----------------
__device__ __forceinline__ bool better(float da, int ia, float db, int ib) {
    return (da < db) || (da == db && ia < ib);
}

// insert candidate into sorted-ascending top4 (registers, static indexing only)
__device__ __forceinline__ void insert4(float (&bd)[4], int (&bi)[4], float d, int j) {
    if (!better(d, j, bd[3], bi[3])) return;
    if (better(d, j, bd[2], bi[2])) {
        bd[3] = bd[2]; bi[3] = bi[2];
        if (better(d, j, bd[1], bi[1])) {
            bd[2] = bd[1]; bi[2] = bi[1];
            if (better(d, j, bd[0], bi[0])) {
                bd[1] = bd[0]; bi[1] = bi[0];
                bd[0] = d; bi[0] = j;
            } else { bd[1] = d; bi[1] = j; }
        } else { bd[2] = d; bi[2] = j; }
    } else { bd[3] = d; bi[3] = j; }
}

// ---------------- K0: pack xyz + squared norm ----------------
__global__ void k_prep(const float* __restrict__ xyz) {
    int i = blockIdx.x * blockDim.x + threadIdx.x;
    if (i >= BB * NN) return;
    float x = xyz[3 * i], y = xyz[3 * i + 1], z = xyz[3 * i + 2];
    float sq = fmaf(x, x, fmaf(y, y, z * z));
    g_xyzw[i] = make_float4(x, y, z, sq);
}

// ---------------- K0b: gather sampled points, emit sampled_xyz output ----------------
__global__ void k_gather(const int* __restrict__ sample, float* __restrict__ out) {
    int i = blockIdx.x * blockDim.x + threadIdx.x;
    if (i >= BB * SS) return;
    int b = i / SS;
    int g = sample[i];
    float4 v = g_xyzw[b * NN + g];
    g_sxyzw[i] = v;
    out[3 * i + 0] = v.x;
    out[3 * i + 1] = v.y;
    out[3 * i + 2] = v.z;
}

// ---------------- K1/K2: top-4 KNN, warp per query, smem-tiled candidates ----------------
template <int NCAND, bool SAMPLED>
__global__ __launch_bounds__(256) void k_knn4() {
    constexpr int TILE = 1024;
    __shared__ float4 tile[TILE];

    const int b    = blockIdx.y;
    const int warp = threadIdx.x >> 5;
    const int lane = threadIdx.x & 31;
    const int q    = blockIdx.x * 8 + warp;

    const float4* cand = (SAMPLED ? g_sxyzw : g_xyzw) + b * NCAND;
    int*   oidx  = (SAMPLED ? g_saidx  : g_aidx)  + (size_t)(b * NCAND + q) * 4;
    float* odist = (SAMPLED ? g_sadist : g_adist) + (size_t)(b * NCAND + q) * 4;

    const float4 qp = cand[q];

    float bd[4] = {CUDART_INF_F, CUDART_INF_F, CUDART_INF_F, CUDART_INF_F};
    int   bi[4] = {0x7fffffff, 0x7fffffff, 0x7fffffff, 0x7fffffff};

    for (int t0 = 0; t0 < NCAND; t0 += TILE) {
        __syncthreads();
        #pragma unroll
        for (int t = threadIdx.x; t < TILE; t += 256)
            tile[t] = cand[t0 + t];
        __syncthreads();

        #pragma unroll 4
        for (int jj = lane; jj < TILE; jj += 32) {
            float4 c = tile[jj];
            float dot = fmaf(qp.x, c.x, fmaf(qp.y, c.y, qp.z * c.z));
            float d2 = fmaxf(qp.w + c.w - 2.0f * dot, 1e-12f);
            insert4(bd, bi, d2, t0 + jj);
        }
    }

    // butterfly merge of sorted top-4 lists across warp
    #pragma unroll
    for (int off = 16; off > 0; off >>= 1) {
        float od[4]; int oi[4];
        #pragma unroll
        for (int k = 0; k < 4; k++) {
            od[k] = __shfl_xor_sync(0xffffffffu, bd[k], off);
            oi[k] = __shfl_xor_sync(0xffffffffu, bi[k], off);
        }
        #pragma unroll
        for (int k = 0; k < 4; k++) insert4(bd, bi, od[k], oi[k]);
    }

    if (lane == 0) {
        #pragma unroll
        for (int k = 0; k < 4; k++) {
            oidx[k]  = bi[k];
            odist[k] = sqrtf(bd[k]);
        }
    }
}

// ---------------- K3: fused 28-feature build + 3-layer MLP ----------------
__global__ __launch_bounds__(128) void k_fused(
    const float* __restrict__ feature,
    const int*   __restrict__ sample,
    const float* __restrict__ w1, const float* __restrict__ b1,
    const float* __restrict__ g1, const float* __restrict__ be1,
    const float* __restrict__ w2, const float* __restrict__ b2,
    const float* __restrict__ g2, const float* __restrict__ be2,
    const float* __restrict__ w3, const float* __restrict__ b3,
    const float* __restrict__ g3, const float* __restrict__ be3,
    float* __restrict__ out)
{
    __shared__ float x28[TP][28];
    __shared__ float t1s[TP][64];
    __shared__ float in2[TP][128];
    __shared__ int sp_g[TP];
    __shared__ int sp_a[TP][4];   // global anchor indices (before)
    __shared__ int sp_ga[TP][4];  // global indices of sampled anchors (after)

    const int tid = threadIdx.x;
    const int blk = blockIdx.x;
    const int b   = blk / (SS / TP);
    const int s0  = (blk % (SS / TP)) * TP;

    if (tid < TP) {
        int p = tid;
        int s = s0 + p;
        int g = sample[b * SS + s];
        sp_g[p] = g;
        #pragma unroll
        for (int k = 0; k < 4; k++) {
            sp_a[p][k] = g_aidx[(b * NN + g) * 4 + k];
            int sa = g_saidx[(b * SS + s) * 4 + k];
            sp_ga[p][k] = sample[b * SS + sa];
        }
        #pragma unroll
        for (int k = 0; k < 3; k++) {
            x28[p][k]     = g_adist[(b * NN + g) * 4 + 1 + k];   // intra_before ch 0..2
            x28[p][6 + k] = g_sadist[(b * SS + s) * 4 + 1 + k];  // intra_after  ch 6..8
        }
    }
    __syncthreads();

    // 22 fresh distances per point: ch 3..5, 9..11, 12..27
    for (int t = tid; t < TP * 22; t += 128) {
        int p = t / 22, w = t % 22;
        int ia, ib, ch;
        if (w < 3) {                 // pairs among a1..a3: (1,2)(1,3)(2,3)
            int pi = (w < 2) ? 1 : 2;
            int pj = (w == 0) ? 2 : 3;
            ia = sp_a[p][pi]; ib = sp_a[p][pj]; ch = 3 + w;
        } else if (w < 6) {          // pairs among ga1..ga3
            int u = w - 3;
            int pi = (u < 2) ? 1 : 2;
            int pj = (u == 0) ? 2 : 3;
            ia = sp_ga[p][pi]; ib = sp_ga[p][pj]; ch = 9 + u;
        } else {                     // inter: i-major over anchors_before, j over anchors_after
            int u = w - 6;
            int i = u >> 2, j = u & 3;
            ia = sp_a[p][i]; ib = sp_ga[p][j]; ch = 12 + u;
        }
        float4 pa = g_xyzw[b * NN + ia];
        float4 pb = g_xyzw[b * NN + ib];
        float dot = fmaf(pa.x, pb.x, fmaf(pa.y, pb.y, pa.z * pb.z));
        float d2 = fmaxf(pa.w + pb.w - 2.0f * dot, 1e-12f);
        x28[p][ch] = sqrtf(d2);
    }

    // gather sampled features into in2[p][0..63]
    for (int t = tid; t < TP * 64; t += 128) {
        int p = t >> 6, c = t & 63;
        in2[p][c] = feature[(size_t)(b * NN + sp_g[p]) * IN_CH + c];
    }
    __syncthreads();

    const float invs = 1.0f / sqrtf(1.0f + 1e-5f);

    // layer 1: 28 -> 64
    if (tid < 64) {
        float acc[TP];
        #pragma unroll
        for (int p = 0; p < TP; p++) acc[p] = b1[tid];
        #pragma unroll
        for (int k = 0; k < 28; k++) {
            float w = w1[k * 64 + tid];
            #pragma unroll
            for (int p = 0; p < TP; p++) acc[p] = fmaf(x28[p][k], w, acc[p]);
        }
        float sc = g1[tid] * invs, sh = be1[tid];
        #pragma unroll
        for (int p = 0; p < TP; p++) {
            float v = fmaf(acc[p], sc, sh);
            t1s[p][tid] = (v >= 0.0f) ? v : 0.2f * v;
        }
    }
    __syncthreads();

    // layer 2: 64 -> 64, output into in2[p][64..127]
    if (tid < 64) {
        float acc[TP];
        #pragma unroll
        for (int p = 0; p < TP; p++) acc[p] = b2[tid];
        #pragma unroll
        for (int k = 0; k < 64; k++) {
            float w = w2[k * 64 + tid];
            #pragma unroll
            for (int p = 0; p < TP; p++) acc[p] = fmaf(t1s[p][k], w, acc[p]);
        }
        float sc = g2[tid] * invs, sh = be2[tid];
        #pragma unroll
        for (int p = 0; p < TP; p++) {
            float v = fmaf(acc[p], sc, sh);
            in2[p][64 + tid] = (v >= 0.0f) ? v : 0.2f * v;
        }
    }
    __syncthreads();

    // layer 3: 128 -> 128
    {
        float acc[TP];
        #pragma unroll
        for (int p = 0; p < TP; p++) acc[p] = b3[tid];
        #pragma unroll
        for (int k = 0; k < 128; k++) {
            float w = w3[k * 128 + tid];
            #pragma unroll
            for (int p = 0; p < TP; p++) acc[p] = fmaf(in2[p][k], w, acc[p]);
        }
        float sc = g3[tid] * invs, sh = be3[tid];
        const size_t obase = (size_t)BB * SS * 3;
        #pragma unroll
        for (int p = 0; p < TP; p++) {
            float v = fmaf(acc[p], sc, sh);
            v = (v >= 0.0f) ? v : 0.2f * v;
            out[obase + (size_t)((b * SS + s0 + p)) * OUT_CH + tid] = v;
        }
    }
}

// ---------------- launch ----------------
extern "C" void kernel_launch(void* const* d_in, const int* in_sizes, int n_in,
                              void* d_out, int out_size) {
    const float* xyz     = (const float*)d_in[0];
    const float* feature = (const float*)d_in[1];
    const int*   sample  = (const int*)d_in[2];
    const float* w1  = (const float*)d_in[3];
    const float* b1  = (const float*)d_in[4];
    const float* g1  = (const float*)d_in[5];
    const float* be1 = (const float*)d_in[6];
    const float* w2  = (const float*)d_in[7];
    const float* b2  = (const float*)d_in[8];
    const float* g2  = (const float*)d_in[9];
    const float* be2 = (const float*)d_in[10];
    const float* w3  = (const float*)d_in[11];
    const float* b3  = (const float*)d_in[12];
    const float* g3  = (const float*)d_in[13];
    const float* be3 = (const float*)d_in[14];
    float* out = (float*)d_out;

    k_prep<<<(BB * NN + 255) / 256, 256>>>(xyz);
    k_gather<<<(BB * SS + 255) / 256, 256>>>(sample, out);

    dim3 gk1(NN / 8, BB);
    k_knn4<NN, false><<<gk1, 256>>>();

    dim3 gk2(SS / 8, BB);
    k_knn4<SS, true><<<gk2, 256>>>();

    k_fused<<<BB * SS / TP, 128>>>(feature, sample,
                                   w1, b1, g1, be1,
                                   w2, b2, g2, be2,
                                   w3, b3, g3, be3,
                                   out);
}